// round 1
// baseline (speedup 1.0000x reference)
#include <cuda_runtime.h>
#include <math.h>

#define BATCH 8
#define SEQ   1024
#define DIM   512
#define HEADS 8
#define DHEAD 64
#define ROWS  (BATCH*SEQ)        // 8192
#define SCALE 0.125f
#define LN_EPS 1e-5f

// ---------------- scratch arena (static device memory, no allocs) ----------
// layout (float offsets):
#define OXN   0u                       // xn   [8192,512]
#define OORN  4194304u                 // orn  [8192,512]
#define OQKV  8388608u                 // qkv  [8192,1536]
#define OORQ  20971520u                // orq  [8192,512]
#define OOMA  25165824u                // 1-alpha^T [8,1024,1024]
#define OATT  33554432u                // attn out pre-Wout [8192,512]
#define OORA  37748736u                // or-attn out pre-Wout [8192,512]
#define OTOT  41943040u

__device__ float g_scratch[OTOT];

// ---------------- LayerNorm: x -> xn, ORquery -> orn -----------------------
__global__ void __launch_bounds__(128) ln_kernel(
    const float* __restrict__ x, const float* __restrict__ oq,
    const float* __restrict__ w, const float* __restrict__ bb,
    float* __restrict__ xn, float* __restrict__ orn)
{
    int row = blockIdx.x;
    const float* src;
    float* dst;
    if (row < ROWS) { src = x  + (size_t)row * DIM;        dst = xn  + (size_t)row * DIM; }
    else            { src = oq + (size_t)(row-ROWS) * DIM; dst = orn + (size_t)(row-ROWS) * DIM; }

    int t = threadIdx.x;                 // 128 threads, 4 floats each
    float4 v = ((const float4*)src)[t];
    float sum = v.x + v.y + v.z + v.w;
    float sq  = v.x*v.x + v.y*v.y + v.z*v.z + v.w*v.w;
    #pragma unroll
    for (int o = 16; o; o >>= 1) {
        sum += __shfl_xor_sync(0xffffffffu, sum, o);
        sq  += __shfl_xor_sync(0xffffffffu, sq,  o);
    }
    __shared__ float s1[4], s2[4];
    if ((t & 31) == 0) { s1[t >> 5] = sum; s2[t >> 5] = sq; }
    __syncthreads();
    sum = s1[0] + s1[1] + s1[2] + s1[3];
    sq  = s2[0] + s2[1] + s2[2] + s2[3];

    float mu  = sum * (1.0f / DIM);
    float var = sq  * (1.0f / DIM) - mu * mu;
    float inv = rsqrtf(var + LN_EPS);

    float4 wv = ((const float4*)w)[t];
    float4 bv = ((const float4*)bb)[t];
    float4 o;
    o.x = (v.x - mu) * inv * wv.x + bv.x;
    o.y = (v.y - mu) * inv * wv.y + bv.y;
    o.z = (v.z - mu) * inv * wv.z + bv.z;
    o.w = (v.w - mu) * inv * wv.w + bv.w;
    ((float4*)dst)[t] = o;
}

// ---------------- oma[b][i][j] = 1 - alpha[b][j][i] ------------------------
__global__ void __launch_bounds__(256) alphat_kernel(
    const float* __restrict__ alpha, float* __restrict__ oma)
{
    __shared__ float t[32][33];
    int bz = blockIdx.z;
    int i0 = blockIdx.x * 32, j0 = blockIdx.y * 32;
    const float* a = alpha + (size_t)bz * SEQ * SEQ;
    float* o = oma + (size_t)bz * SEQ * SEQ;
    int tx = threadIdx.x, ty = threadIdx.y;   // (32, 8)
    #pragma unroll
    for (int k = 0; k < 32; k += 8)
        t[ty + k][tx] = a[(size_t)(j0 + ty + k) * SEQ + i0 + tx];
    __syncthreads();
    #pragma unroll
    for (int k = 0; k < 32; k += 8)
        o[(size_t)(i0 + ty + k) * SEQ + j0 + tx] = 1.0f - t[tx][ty + k];
}

// ---------------- SGEMM C[M,Ncols] = A[M,512] @ Bw[512,Ncols] --------------
// 128x128 tile, BK=16, 256 threads, 8x8 microtile, strided mapping.
__global__ void __launch_bounds__(256) sgemm512(
    const float* __restrict__ A, const float* __restrict__ Bw,
    float* __restrict__ C, int Ncols)
{
    __shared__ float As[128][16];
    __shared__ float Bs[16][128];
    int bm = blockIdx.y * 128, bn = blockIdx.x * 128;
    int tid = threadIdx.x;
    int tx = tid & 15, ty = tid >> 4;

    float acc[8][8];
    #pragma unroll
    for (int r = 0; r < 8; r++)
        #pragma unroll
        for (int c = 0; c < 8; c++) acc[r][c] = 0.f;

    int arow = tid >> 1,  acol = (tid & 1) * 8;
    int brow = tid >> 4,  bcol = (tid & 15) * 8;
    const float* Ag = A  + (size_t)(bm + arow) * 512 + acol;
    const float* Bg = Bw + (size_t)brow * Ncols + bn + bcol;

    for (int k0 = 0; k0 < 512; k0 += 16) {
        float4 a0 = *(const float4*)(Ag);
        float4 a1 = *(const float4*)(Ag + 4);
        float4 b0 = *(const float4*)(Bg);
        float4 b1 = *(const float4*)(Bg + 4);
        *(float4*)(&As[arow][acol])     = a0;
        *(float4*)(&As[arow][acol + 4]) = a1;
        *(float4*)(&Bs[brow][bcol])     = b0;
        *(float4*)(&Bs[brow][bcol + 4]) = b1;
        __syncthreads();
        #pragma unroll
        for (int kk = 0; kk < 16; kk++) {
            float a[8], b[8];
            #pragma unroll
            for (int r = 0; r < 8; r++) a[r] = As[ty + 16*r][kk];
            #pragma unroll
            for (int c = 0; c < 8; c++) b[c] = Bs[kk][tx + 16*c];
            #pragma unroll
            for (int r = 0; r < 8; r++)
                #pragma unroll
                for (int c = 0; c < 8; c++) acc[r][c] += a[r] * b[c];
        }
        __syncthreads();
        Ag += 16;
        Bg += (size_t)16 * Ncols;
    }
    #pragma unroll
    for (int r = 0; r < 8; r++) {
        float* crow = C + (size_t)(bm + ty + 16*r) * Ncols + bn;
        #pragma unroll
        for (int c = 0; c < 8; c++) crow[tx + 16*c] = acc[r][c];
    }
}

// ---------------- fused flash attention (both passes) ----------------------
// grid: (SEQ/64, HEADS, BATCH*2)   z = b*2 + orpass
// block: 256 threads, 4x4 microtile over 64 queries x 64 keys.
// smem: Qs, Ks, Vs, Ps each [64][65] floats (dynamic, 66560 B)
__global__ void __launch_bounds__(256) attn_kernel(
    const float* __restrict__ qkv, const float* __restrict__ orq,
    const float* __restrict__ oma, float* __restrict__ att, float* __restrict__ oratt)
{
    extern __shared__ float sm[];
    float* Qs = sm;                  // 64*65
    float* Ks = sm + 4160;
    float* Vs = sm + 8320;
    float* Ps = sm + 12480;

    int qt = blockIdx.x, h = blockIdx.y;
    int b = blockIdx.z >> 1, orp = blockIdx.z & 1;
    int tid = threadIdx.x, tx = tid & 15, ty = tid >> 4;
    int qi0 = qt * 64;

    int qld = orp ? 512 : 1536;
    const float* qbase = (orp ? orq : qkv) + (size_t)(b * SEQ + qi0) * qld + h * DHEAD;
    #pragma unroll
    for (int i = 0; i < 4; i++) {
        int vi = tid + 256 * i; int row = vi >> 4; int c = (vi & 15) * 4;
        float4 v = *(const float4*)(qbase + (size_t)row * qld + c);
        float* q = Qs + row * 65 + c;
        q[0] = v.x; q[1] = v.y; q[2] = v.z; q[3] = v.w;
    }

    float m[4], l[4], acc[4][4];
    #pragma unroll
    for (int r = 0; r < 4; r++) {
        m[r] = -1e30f; l[r] = 0.f;
        #pragma unroll
        for (int c = 0; c < 4; c++) acc[r][c] = 0.f;
    }

    const float* kbase = qkv + (size_t)(b * SEQ) * 1536 + 512  + h * DHEAD;
    const float* vbase = qkv + (size_t)(b * SEQ) * 1536 + 1024 + h * DHEAD;
    const float* ab = oma + (size_t)b * SEQ * SEQ;

    for (int kt = 0; kt < 16; kt++) {
        int kj0 = kt * 64;
        __syncthreads();
        #pragma unroll
        for (int i = 0; i < 4; i++) {
            int vi = tid + 256 * i; int row = vi >> 4; int c = (vi & 15) * 4;
            float4 kv = *(const float4*)(kbase + (size_t)(kj0 + row) * 1536 + c);
            float* p = Ks + row * 65 + c;
            p[0] = kv.x; p[1] = kv.y; p[2] = kv.z; p[3] = kv.w;
            float4 vv = *(const float4*)(vbase + (size_t)(kj0 + row) * 1536 + c);
            p = Vs + row * 65 + c;
            p[0] = vv.x; p[1] = vv.y; p[2] = vv.z; p[3] = vv.w;
        }
        __syncthreads();

        float s[4][4];
        #pragma unroll
        for (int r = 0; r < 4; r++)
            #pragma unroll
            for (int c = 0; c < 4; c++) s[r][c] = 0.f;

        #pragma unroll 8
        for (int k = 0; k < 64; k++) {
            float qa[4], kb[4];
            #pragma unroll
            for (int r = 0; r < 4; r++) qa[r] = Qs[(ty + 16*r) * 65 + k];
            #pragma unroll
            for (int c = 0; c < 4; c++) kb[c] = Ks[(tx + 16*c) * 65 + k];
            #pragma unroll
            for (int r = 0; r < 4; r++)
                #pragma unroll
                for (int c = 0; c < 4; c++) s[r][c] += qa[r] * kb[c];
        }

        // scale + OR-pass logit modification
        #pragma unroll
        for (int r = 0; r < 4; r++) {
            #pragma unroll
            for (int c = 0; c < 4; c++) {
                float sv = s[r][c] * SCALE;
                if (orp) {
                    int qi = qi0 + ty + 16*r;
                    int kj = kj0 + tx + 16*c;
                    float om = ab[(size_t)qi * SEQ + kj];
                    if (qi == kj) sv = 0.f;
                    sv *= om;
                }
                s[r][c] = sv;
            }
        }

        // online softmax (per query row; 16 lanes share each row group via ty)
        #pragma unroll
        for (int r = 0; r < 4; r++) {
            float rm = fmaxf(fmaxf(s[r][0], s[r][1]), fmaxf(s[r][2], s[r][3]));
            rm = fmaxf(rm, __shfl_xor_sync(0xffffffffu, rm, 1));
            rm = fmaxf(rm, __shfl_xor_sync(0xffffffffu, rm, 2));
            rm = fmaxf(rm, __shfl_xor_sync(0xffffffffu, rm, 4));
            rm = fmaxf(rm, __shfl_xor_sync(0xffffffffu, rm, 8));
            float mn = fmaxf(m[r], rm);
            float corr = __expf(m[r] - mn);
            float rs = 0.f;
            #pragma unroll
            for (int c = 0; c < 4; c++) {
                float e = __expf(s[r][c] - mn);
                s[r][c] = e; rs += e;
            }
            rs += __shfl_xor_sync(0xffffffffu, rs, 1);
            rs += __shfl_xor_sync(0xffffffffu, rs, 2);
            rs += __shfl_xor_sync(0xffffffffu, rs, 4);
            rs += __shfl_xor_sync(0xffffffffu, rs, 8);
            l[r] = l[r] * corr + rs;
            m[r] = mn;
            #pragma unroll
            for (int c = 0; c < 4; c++) acc[r][c] *= corr;
        }

        #pragma unroll
        for (int r = 0; r < 4; r++)
            #pragma unroll
            for (int c = 0; c < 4; c++)
                Ps[(ty + 16*r) * 65 + tx + 16*c] = s[r][c];
        __syncthreads();

        #pragma unroll 8
        for (int k = 0; k < 64; k++) {
            float pr[4], vv[4];
            #pragma unroll
            for (int r = 0; r < 4; r++) pr[r] = Ps[(ty + 16*r) * 65 + k];
            #pragma unroll
            for (int c = 0; c < 4; c++) vv[c] = Vs[k * 65 + tx + 16*c];
            #pragma unroll
            for (int r = 0; r < 4; r++)
                #pragma unroll
                for (int c = 0; c < 4; c++) acc[r][c] += pr[r] * vv[c];
        }
    }

    float* ob = (orp ? oratt : att) + (size_t)(b * SEQ + qi0) * 512 + h * DHEAD;
    #pragma unroll
    for (int r = 0; r < 4; r++) {
        float inv = 1.0f / l[r];
        #pragma unroll
        for (int c = 0; c < 4; c++)
            ob[(size_t)(ty + 16*r) * 512 + tx + 16*c] = acc[r][c] * inv;
    }
}

// ---------------------------------------------------------------------------
extern "C" void kernel_launch(void* const* d_in, const int* in_sizes, int n_in,
                              void* d_out, int out_size)
{
    const float* x     = (const float*)d_in[0];
    const float* oq    = (const float*)d_in[1];
    const float* alpha = (const float*)d_in[2];
    const float* lnw   = (const float*)d_in[3];
    const float* lnb   = (const float*)d_in[4];
    const float* wqkv  = (const float*)d_in[5];
    const float* worq  = (const float*)d_in[6];
    const float* wout  = (const float*)d_in[7];
    float* out = (float*)d_out;

    void* sp = nullptr;
    cudaGetSymbolAddress(&sp, g_scratch);
    float* S = (float*)sp;
    float* xn   = S + OXN;
    float* orn  = S + OORN;
    float* qkv  = S + OQKV;
    float* orqb = S + OORQ;
    float* oma  = S + OOMA;
    float* att  = S + OATT;
    float* orat = S + OORA;

    ln_kernel<<<2 * ROWS, 128>>>(x, oq, lnw, lnb, xn, orn);
    alphat_kernel<<<dim3(32, 32, 8), dim3(32, 8)>>>(alpha, oma);
    sgemm512<<<dim3(12, 64), 256>>>(xn,  wqkv, qkv,  1536);
    sgemm512<<<dim3(4, 64),  256>>>(orn, worq, orqb, 512);

    const int ATTN_SMEM = 4 * 4160 * 4;  // 66560 B
    cudaFuncSetAttribute(attn_kernel, cudaFuncAttributeMaxDynamicSharedMemorySize, ATTN_SMEM);
    attn_kernel<<<dim3(16, HEADS, BATCH * 2), 256, ATTN_SMEM>>>(qkv, orqb, oma, att, orat);

    sgemm512<<<dim3(4, 64), 256>>>(att,  wout, out,            512);
    sgemm512<<<dim3(4, 64), 256>>>(orat, wout, out + 4194304,  512);
}

// round 3
// speedup vs baseline: 1.6318x; 1.6318x over previous
#include <cuda_runtime.h>
#include <math.h>

#define BATCH 8
#define SEQ   1024
#define DIM   512
#define HEADS 8
#define DHEAD 64
#define ROWS  (BATCH*SEQ)        // 8192
#define SCALE 0.125f
#define LN_EPS 1e-5f

// ---------------- scratch arena (float offsets) ----------------------------
#define OXN   0u                       // xn   [8192,512]
#define OORN  4194304u                 // orn  [8192,512]
#define OQKV  8388608u                 // qkv  [8192,1536]
#define OORQ  20971520u                // orq  [8192,512]
#define OATT  25165824u                // attn out pre-Wout [8192,512]
#define OORA  29360128u                // or-attn out pre-Wout [8192,512]
#define OTOT  33554432u

__device__ float g_scratch[OTOT];

// ---------------- helpers ---------------------------------------------------
__device__ __forceinline__ unsigned f2tf(float f) {
    unsigned u;
    asm("cvt.rna.tf32.f32 %0, %1;" : "=r"(u) : "f"(f));
    return u;
}
__device__ __forceinline__ void mma_tf32(float* c, const unsigned* a,
                                         unsigned b0, unsigned b1) {
    asm volatile(
        "mma.sync.aligned.m16n8k8.row.col.f32.tf32.tf32.f32 "
        "{%0,%1,%2,%3}, {%4,%5,%6,%7}, {%8,%9}, {%0,%1,%2,%3};"
        : "+f"(c[0]), "+f"(c[1]), "+f"(c[2]), "+f"(c[3])
        : "r"(a[0]), "r"(a[1]), "r"(a[2]), "r"(a[3]), "r"(b0), "r"(b1));
}

// ---------------- LayerNorm: x -> xn, ORquery -> orn -----------------------
__global__ void __launch_bounds__(128) ln_kernel(
    const float* __restrict__ x, const float* __restrict__ oq,
    const float* __restrict__ w, const float* __restrict__ bb,
    float* __restrict__ xn, float* __restrict__ orn)
{
    int row = blockIdx.x;
    const float* src;
    float* dst;
    if (row < ROWS) { src = x  + (size_t)row * DIM;        dst = xn  + (size_t)row * DIM; }
    else            { src = oq + (size_t)(row-ROWS) * DIM; dst = orn + (size_t)(row-ROWS) * DIM; }

    int t = threadIdx.x;
    float4 v = ((const float4*)src)[t];
    float sum = v.x + v.y + v.z + v.w;
    float sq  = v.x*v.x + v.y*v.y + v.z*v.z + v.w*v.w;
    #pragma unroll
    for (int o = 16; o; o >>= 1) {
        sum += __shfl_xor_sync(0xffffffffu, sum, o);
        sq  += __shfl_xor_sync(0xffffffffu, sq,  o);
    }
    __shared__ float s1[4], s2[4];
    if ((t & 31) == 0) { s1[t >> 5] = sum; s2[t >> 5] = sq; }
    __syncthreads();
    sum = s1[0] + s1[1] + s1[2] + s1[3];
    sq  = s2[0] + s2[1] + s2[2] + s2[3];

    float mu  = sum * (1.0f / DIM);
    float var = sq  * (1.0f / DIM) - mu * mu;
    float inv = rsqrtf(var + LN_EPS);

    float4 wv = ((const float4*)w)[t];
    float4 bv = ((const float4*)bb)[t];
    float4 o;
    o.x = (v.x - mu) * inv * wv.x + bv.x;
    o.y = (v.y - mu) * inv * wv.y + bv.y;
    o.z = (v.z - mu) * inv * wv.z + bv.z;
    o.w = (v.w - mu) * inv * wv.w + bv.w;
    ((float4*)dst)[t] = o;
}

// ---------------- SGEMM C[M,Ncols] = A[M,512] @ Bw[512,Ncols] --------------
__global__ void __launch_bounds__(256) sgemm512(
    const float* __restrict__ A, const float* __restrict__ Bw,
    float* __restrict__ C, int Ncols)
{
    __shared__ float As[128][16];
    __shared__ float Bs[16][128];
    int bm = blockIdx.y * 128, bn = blockIdx.x * 128;
    int tid = threadIdx.x;
    int tx = tid & 15, ty = tid >> 4;

    float acc[8][8];
    #pragma unroll
    for (int r = 0; r < 8; r++)
        #pragma unroll
        for (int c = 0; c < 8; c++) acc[r][c] = 0.f;

    int arow = tid >> 1,  acol = (tid & 1) * 8;
    int brow = tid >> 4,  bcol = (tid & 15) * 8;
    const float* Ag = A  + (size_t)(bm + arow) * 512 + acol;
    const float* Bg = Bw + (size_t)brow * Ncols + bn + bcol;

    for (int k0 = 0; k0 < 512; k0 += 16) {
        float4 a0 = *(const float4*)(Ag);
        float4 a1 = *(const float4*)(Ag + 4);
        float4 b0 = *(const float4*)(Bg);
        float4 b1 = *(const float4*)(Bg + 4);
        *(float4*)(&As[arow][acol])     = a0;
        *(float4*)(&As[arow][acol + 4]) = a1;
        *(float4*)(&Bs[brow][bcol])     = b0;
        *(float4*)(&Bs[brow][bcol + 4]) = b1;
        __syncthreads();
        #pragma unroll
        for (int kk = 0; kk < 16; kk++) {
            float a[8], b[8];
            #pragma unroll
            for (int r = 0; r < 8; r++) a[r] = As[ty + 16*r][kk];
            #pragma unroll
            for (int c = 0; c < 8; c++) b[c] = Bs[kk][tx + 16*c];
            #pragma unroll
            for (int r = 0; r < 8; r++)
                #pragma unroll
                for (int c = 0; c < 8; c++) acc[r][c] += a[r] * b[c];
        }
        __syncthreads();
        Ag += 16;
        Bg += (size_t)16 * Ncols;
    }
    #pragma unroll
    for (int r = 0; r < 8; r++) {
        float* crow = C + (size_t)(bm + ty + 16*r) * Ncols + bn;
        #pragma unroll
        for (int c = 0; c < 8; c++) crow[tx + 16*c] = acc[r][c];
    }
}

// ---------------- flash attention on tf32 mma.sync --------------------------
// grid: (SEQ/128, HEADS, BATCH*2)  z = b*2 + orpass ; block: 256 (8 warps)
// Each warp: 16 q rows. Q lives in A-fragments (regs). K/V tf32 in smem.
// smem: Ks[64][68] u32, Vs[64][72] u32, Ps[8][16][68] u32  => 70656 B
#define KPAD 68
#define VPAD 72
__global__ void __launch_bounds__(256) attn_kernel(
    const float* __restrict__ qkv, const float* __restrict__ orq,
    const float* __restrict__ alpha, float* __restrict__ att, float* __restrict__ oratt)
{
    extern __shared__ unsigned sm[];
    unsigned* Ks = sm;                       // 64*68
    unsigned* Vs = sm + 64*KPAD;             // 64*72
    unsigned* PsAll = Vs + 64*VPAD;          // 8 * 16*68

    int tid = threadIdx.x;
    int w   = tid >> 5;
    int lane = tid & 31;
    int g = lane >> 2;          // group id 0..7
    int q4 = lane & 3;          // 0..3
    unsigned* Ps = PsAll + w * (16 * KPAD);

    int qt = blockIdx.x, h = blockIdx.y;
    int b = blockIdx.z >> 1, orp = blockIdx.z & 1;
    int qi0 = qt * 128;
    int r0 = qi0 + 16 * w;      // this warp's first q row

    // ---- load Q into A fragments (tf32), once ----
    int qld = orp ? DIM : 3*DIM;
    const float* qbase = (orp ? orq : qkv) + (size_t)(b * SEQ) * qld + h * DHEAD;
    unsigned qa[8][4];
    #pragma unroll
    for (int s = 0; s < 8; s++) {
        int c0 = 8*s + q4;
        const float* row0 = qbase + (size_t)(r0 + g)     * qld;
        const float* row8 = qbase + (size_t)(r0 + g + 8) * qld;
        qa[s][0] = f2tf(row0[c0]);
        qa[s][1] = f2tf(row8[c0]);
        qa[s][2] = f2tf(row0[c0 + 4]);
        qa[s][3] = f2tf(row8[c0 + 4]);
    }

    float m0 = -1e30f, m1 = -1e30f, l0 = 0.f, l1 = 0.f;
    float oacc[8][4];
    #pragma unroll
    for (int nt = 0; nt < 8; nt++)
        #pragma unroll
        for (int j = 0; j < 4; j++) oacc[nt][j] = 0.f;

    const float* kbase = qkv + (size_t)(b * SEQ) * 1536 + 512  + h * DHEAD;
    const float* vbase = qkv + (size_t)(b * SEQ) * 1536 + 1024 + h * DHEAD;
    const float* ab = alpha + (size_t)b * SEQ * SEQ;

    for (int kt = 0; kt < 16; kt++) {
        int kj0 = kt * 64;
        __syncthreads();
        // ---- cooperative K/V load -> tf32 smem ----
        #pragma unroll
        for (int it = 0; it < 4; it++) {
            int idx = tid + 256 * it;          // 0..1023
            int row = idx >> 4;
            int c4  = (idx & 15) << 2;
            float4 kv = *(const float4*)(kbase + (size_t)(kj0 + row) * 1536 + c4);
            unsigned* kp = Ks + row * KPAD + c4;
            kp[0] = f2tf(kv.x); kp[1] = f2tf(kv.y); kp[2] = f2tf(kv.z); kp[3] = f2tf(kv.w);
            float4 vv = *(const float4*)(vbase + (size_t)(kj0 + row) * 1536 + c4);
            unsigned* vp = Vs + row * VPAD + c4;
            vp[0] = f2tf(vv.x); vp[1] = f2tf(vv.y); vp[2] = f2tf(vv.z); vp[3] = f2tf(vv.w);
        }
        __syncthreads();

        // ---- S = Q @ K^T : 8 ksteps x 8 ntiles ----
        float c[8][4];
        #pragma unroll
        for (int nt = 0; nt < 8; nt++)
            #pragma unroll
            for (int j = 0; j < 4; j++) c[nt][j] = 0.f;

        #pragma unroll
        for (int s = 0; s < 8; s++) {
            #pragma unroll
            for (int nt = 0; nt < 8; nt++) {
                unsigned b0 = Ks[(8*nt + g) * KPAD + 8*s + q4];
                unsigned b1 = Ks[(8*nt + g) * KPAD + 8*s + q4 + 4];
                mma_tf32(c[nt], qa[s], b0, b1);
            }
        }

        // ---- scale + OR-pass logit modification ----
        if (!orp) {
            #pragma unroll
            for (int nt = 0; nt < 8; nt++)
                #pragma unroll
                for (int j = 0; j < 4; j++) c[nt][j] *= SCALE;
        } else {
            int qiA = r0 + g, qiB = r0 + g + 8;
            #pragma unroll
            for (int nt = 0; nt < 8; nt++) {
                int kjE = kj0 + 8*nt + 2*q4;      // even col
                int kjO = kjE + 1;
                float aEA = __ldg(ab + (size_t)kjE * SEQ + qiA);
                float aOA = __ldg(ab + (size_t)kjO * SEQ + qiA);
                float aEB = __ldg(ab + (size_t)kjE * SEQ + qiB);
                float aOB = __ldg(ab + (size_t)kjO * SEQ + qiB);
                float v0 = c[nt][0] * SCALE; if (qiA == kjE) v0 = 0.f;
                float v1 = c[nt][1] * SCALE; if (qiA == kjO) v1 = 0.f;
                float v2 = c[nt][2] * SCALE; if (qiB == kjE) v2 = 0.f;
                float v3 = c[nt][3] * SCALE; if (qiB == kjO) v3 = 0.f;
                c[nt][0] = v0 * (1.f - aEA);
                c[nt][1] = v1 * (1.f - aOA);
                c[nt][2] = v2 * (1.f - aEB);
                c[nt][3] = v3 * (1.f - aOB);
            }
        }

        // ---- online softmax (rows g and g+8 per thread) ----
        float rm0 = -1e30f, rm1 = -1e30f;
        #pragma unroll
        for (int nt = 0; nt < 8; nt++) {
            rm0 = fmaxf(rm0, fmaxf(c[nt][0], c[nt][1]));
            rm1 = fmaxf(rm1, fmaxf(c[nt][2], c[nt][3]));
        }
        rm0 = fmaxf(rm0, __shfl_xor_sync(0xffffffffu, rm0, 1));
        rm0 = fmaxf(rm0, __shfl_xor_sync(0xffffffffu, rm0, 2));
        rm1 = fmaxf(rm1, __shfl_xor_sync(0xffffffffu, rm1, 1));
        rm1 = fmaxf(rm1, __shfl_xor_sync(0xffffffffu, rm1, 2));
        float mn0 = fmaxf(m0, rm0), mn1 = fmaxf(m1, rm1);
        float corr0 = __expf(m0 - mn0), corr1 = __expf(m1 - mn1);
        m0 = mn0; m1 = mn1;

        float rs0 = 0.f, rs1 = 0.f;
        #pragma unroll
        for (int nt = 0; nt < 8; nt++) {
            float e0 = __expf(c[nt][0] - mn0);
            float e1 = __expf(c[nt][1] - mn0);
            float e2 = __expf(c[nt][2] - mn1);
            float e3 = __expf(c[nt][3] - mn1);
            rs0 += e0 + e1; rs1 += e2 + e3;
            // store P (tf32) to per-warp smem buffer
            unsigned* p0 = Ps + g * KPAD + 8*nt + 2*q4;
            p0[0] = f2tf(e0); p0[1] = f2tf(e1);
            unsigned* p1 = Ps + (g + 8) * KPAD + 8*nt + 2*q4;
            p1[0] = f2tf(e2); p1[1] = f2tf(e3);
        }
        rs0 += __shfl_xor_sync(0xffffffffu, rs0, 1);
        rs0 += __shfl_xor_sync(0xffffffffu, rs0, 2);
        rs1 += __shfl_xor_sync(0xffffffffu, rs1, 1);
        rs1 += __shfl_xor_sync(0xffffffffu, rs1, 2);
        l0 = l0 * corr0 + rs0;
        l1 = l1 * corr1 + rs1;
        #pragma unroll
        for (int nt = 0; nt < 8; nt++) {
            oacc[nt][0] *= corr0; oacc[nt][1] *= corr0;
            oacc[nt][2] *= corr1; oacc[nt][3] *= corr1;
        }
        __syncwarp();

        // ---- O += P @ V : k = key dim ----
        #pragma unroll
        for (int s = 0; s < 8; s++) {
            unsigned pa[4];
            pa[0] = Ps[g * KPAD + 8*s + q4];
            pa[1] = Ps[(g + 8) * KPAD + 8*s + q4];
            pa[2] = Ps[g * KPAD + 8*s + q4 + 4];
            pa[3] = Ps[(g + 8) * KPAD + 8*s + q4 + 4];
            #pragma unroll
            for (int nt = 0; nt < 8; nt++) {
                unsigned b0 = Vs[(8*s + q4) * VPAD + 8*nt + g];
                unsigned b1 = Vs[(8*s + q4 + 4) * VPAD + 8*nt + g];
                mma_tf32(oacc[nt], pa, b0, b1);
            }
        }
    }

    // ---- epilogue ----
    float inv0 = 1.0f / l0, inv1 = 1.0f / l1;
    float* ob = (orp ? oratt : att) + (size_t)(b * SEQ) * DIM + h * DHEAD;
    float* rowA = ob + (size_t)(r0 + g)     * DIM;
    float* rowB = ob + (size_t)(r0 + g + 8) * DIM;
    #pragma unroll
    for (int nt = 0; nt < 8; nt++) {
        int col = 8*nt + 2*q4;
        float2 vA = make_float2(oacc[nt][0] * inv0, oacc[nt][1] * inv0);
        float2 vB = make_float2(oacc[nt][2] * inv1, oacc[nt][3] * inv1);
        *(float2*)(rowA + col) = vA;
        *(float2*)(rowB + col) = vB;
    }
}

// ---------------------------------------------------------------------------
extern "C" void kernel_launch(void* const* d_in, const int* in_sizes, int n_in,
                              void* d_out, int out_size)
{
    const float* x     = (const float*)d_in[0];
    const float* oq    = (const float*)d_in[1];
    const float* alpha = (const float*)d_in[2];
    const float* lnw   = (const float*)d_in[3];
    const float* lnb   = (const float*)d_in[4];
    const float* wqkv  = (const float*)d_in[5];
    const float* worq  = (const float*)d_in[6];
    const float* wout  = (const float*)d_in[7];
    float* out = (float*)d_out;

    void* sp = nullptr;
    cudaGetSymbolAddress(&sp, g_scratch);
    float* S = (float*)sp;
    float* xn   = S + OXN;
    float* orn  = S + OORN;
    float* qkv  = S + OQKV;
    float* orqb = S + OORQ;
    float* att  = S + OATT;
    float* orat = S + OORA;

    ln_kernel<<<2 * ROWS, 128>>>(x, oq, lnw, lnb, xn, orn);
    sgemm512<<<dim3(12, 64), 256>>>(xn,  wqkv, qkv,  1536);
    sgemm512<<<dim3(4, 64),  256>>>(orn, worq, orqb, 512);

    const int ATTN_SMEM = (64*KPAD + 64*VPAD + 8*16*KPAD) * 4;  // 70656 B
    cudaFuncSetAttribute(attn_kernel, cudaFuncAttributeMaxDynamicSharedMemorySize, ATTN_SMEM);
    attn_kernel<<<dim3(8, HEADS, BATCH * 2), 256, ATTN_SMEM>>>(qkv, orqb, alpha, att, orat);

    sgemm512<<<dim3(4, 64), 256>>>(att,  wout, out,            512);
    sgemm512<<<dim3(4, 64), 256>>>(orat, wout, out + 4194304,  512);
}